// round 10
// baseline (speedup 1.0000x reference)
#include <cuda_runtime.h>
#include <cstdint>
#include <math.h>

#define N     16384
#define BKT   16384         // buckets (lambda = 1)
#define NB    8             // CTAs in ONE cluster
#define TPB   1024          // 8192 threads, 2 items each
#define HPC   (BKT / NB)    // 2048 histogram entries owned per CTA (re-zero)
#define EPT   (BKT / TPB)   // 16 histogram entries scanned per thread

#define SCALE     16777216.0f            // 2^24 fixed-point for e
#define INV_SCALE 5.9604644775390625e-8f // 2^-24

// ---- global scratch (L2; zero-init at load; re-zeroed each run) ----
__device__ unsigned long long g_H[BKT];  // (fixed_sum << 20) | count
__device__ float2 g_sorted[N];           // {duration, exp(theta)}; overwritten

// dynamic smem: Wp float[BKT] @0 (64KB), S ushort[BKT+2] @65536 (~32KB)
#define SMEM_BYTES (65536 + 32768 + 64)
extern __shared__ char smem_raw[];

__device__ __forceinline__ void cluster_sync() {
    // arrive = release, wait = acquire at cluster scope: no explicit fences
    asm volatile("barrier.cluster.arrive.aligned;" ::: "memory");
    asm volatile("barrier.cluster.wait.aligned;" ::: "memory");
}

__device__ __forceinline__ int bucket_of(float d) {
    int b = (int)(d * (float)BKT);
    if (b >= BKT) b = BKT - 1;
    if (b < 0) b = 0;
    return b;
}

__global__ void __launch_bounds__(TPB, 1) __cluster_dims__(NB, 1, 1)
cox_cluster_kernel(const float* __restrict__ theta,
                   const float* __restrict__ dur,
                   const float* __restrict__ ev,
                   float* __restrict__ out) {
    float*          Wp = (float*)(smem_raw);            // excl. weight prefix
    unsigned short* S  = (unsigned short*)(smem_raw + 65536); // bucket starts

    __shared__ float warpTotF[32];
    __shared__ float warpPreF[32];
    __shared__ int   warpTotI[32];
    __shared__ int   warpPreI[32];
    __shared__ float s_total;

    const int t    = threadIdx.x;
    const int k    = blockIdx.x;
    const int g    = k * TPB + t;
    const int lane = t & 31;
    const int wid  = t >> 5;

    // ---- Pass A: one packed 64-bit atomic per item; rank from return ----
    const int i0 = g;
    const int i1 = g + NB * TPB;
    float th0 = theta[i0], th1 = theta[i1];
    float d0  = dur[i0],   d1  = dur[i1];
    float ev0 = ev[i0],    ev1 = ev[i1];
    float e0  = __expf(th0), e1 = __expf(th1);
    int   b0  = bucket_of(d0), b1 = bucket_of(d1);
    unsigned long long p0 =
        ((unsigned long long)__float2ull_rn(e0 * SCALE) << 20) | 1ull;
    unsigned long long p1 =
        ((unsigned long long)__float2ull_rn(e1 * SCALE) << 20) | 1ull;
    unsigned long long o0 = atomicAdd(&g_H[b0], p0);
    unsigned long long o1 = atomicAdd(&g_H[b1], p1);
    int rank0 = (int)(o0 & 0xFFFFFull);
    int rank1 = (int)(o1 & 0xFFFFFull);
    float acc = ev0 * th0 + ev1 * th1;
    if (g == 0) out[0] = 0.0f;             // ordered before final adds by B1/B2
    cluster_sync();                                            // B1

    // ---- Scan: every CTA redundantly scans all 16384 packed entries ----
    // thread t owns contiguous entries [16t, 16t+16)
    float wv[EPT]; int cv[EPT];
    const int e8 = t * EPT;
    {
        const ulonglong2* H2 = (const ulonglong2*)&g_H[e8];
        #pragma unroll
        for (int j = 0; j < EPT / 2; ++j) {
            ulonglong2 h = __ldcg(&H2[j]);
            wv[2*j]   = (float)(h.x >> 20) * INV_SCALE;
            cv[2*j]   = (int)(h.x & 0xFFFFFull);
            wv[2*j+1] = (float)(h.y >> 20) * INV_SCALE;
            cv[2*j+1] = (int)(h.y & 0xFFFFFull);
        }
    }
    float runW = 0.0f; int runC = 0;
    #pragma unroll
    for (int j = 0; j < EPT; ++j) { runW += wv[j]; runC += cv[j]; }
    float iW = runW; int iC = runC;
    #pragma unroll
    for (int off = 1; off < 32; off <<= 1) {
        float uW = __shfl_up_sync(0xFFFFFFFFu, iW, off);
        int   uC = __shfl_up_sync(0xFFFFFFFFu, iC, off);
        if (lane >= off) { iW += uW; iC += uC; }
    }
    if (lane == 31) { warpTotF[wid] = iW; warpTotI[wid] = iC; }
    __syncthreads();
    if (wid == 0) {
        float vF = warpTotF[lane]; int vI = warpTotI[lane];
        float wF = vF; int wI = vI;
        #pragma unroll
        for (int off = 1; off < 32; off <<= 1) {
            float uF = __shfl_up_sync(0xFFFFFFFFu, wF, off);
            int   uI = __shfl_up_sync(0xFFFFFFFFu, wI, off);
            if (lane >= off) { wF += uF; wI += uI; }
        }
        warpPreF[lane] = wF - vF;
        warpPreI[lane] = wI - vI;
        if (lane == 31) s_total = wF;
    }
    __syncthreads();
    float eW = warpPreF[wid] + (iW - runW);   // exclusive prefix at e8
    int   eC = warpPreI[wid] + (iC - runC);
    #pragma unroll
    for (int j = 0; j < EPT; ++j) {
        Wp[e8 + j] = eW;
        S[e8 + j]  = (unsigned short)eC;
        eW += wv[j];
        eC += cv[j];
    }
    if (t == 0) S[BKT] = (unsigned short)0;   // unused sentinel slot guard
    if (t == TPB - 1) S[BKT] = (unsigned short)(N & 0xFFFF); // start of bkt BKT = N... (N==16384 fits)
    const float total = s_total;
    __syncthreads();

    // ---- Pass B: scatter via precomputed rank (NO atomics) ----
    g_sorted[(int)S[b0] + rank0] = make_float2(d0, e0);
    g_sorted[(int)S[b1] + rank1] = make_float2(d1, e1);
    cluster_sync();                                            // B2

    // ---- re-zero owned histogram segment (all reads done before B2) ----
    g_H[k * HPC + t] = 0ull;
    g_H[k * HPC + t + TPB] = 0ull;

    // ---- Phase 4: per-item risk (starts/prefix from smem, items from L2) ----
    #pragma unroll
    for (int u = 0; u < 2; ++u) {
        float d  = (u == 0) ? d0  : d1;
        float e_ = (u == 0) ? ev0 : ev1;
        int   b  = (u == 0) ? b0  : b1;
        int s0 = (int)S[b];
        int s1 = (b == BKT - 1) ? N : (int)S[b + 1];
        float Sa = Wp[b];
        for (int s = s0; s < s1; ++s) {
            float2 v = __ldcg(&g_sorted[s]);
            if (v.x < d) Sa += v.y;           // strict <: self & ties excluded
        }
        float risk = total - Sa;              // sum over d_j >= d_i
        acc -= e_ * __logf(risk);
    }
    #pragma unroll
    for (int off = 16; off > 0; off >>= 1)
        acc += __shfl_down_sync(0xFFFFFFFFu, acc, off);
    if (lane == 0) atomicAdd(out, -acc / (float)N);
    // kernel exit flushes atomics; g_H left zeroed for next replay
}

extern "C" void kernel_launch(void* const* d_in, const int* in_sizes, int n_in,
                              void* d_out, int out_size) {
    const float* theta = (const float*)d_in[0];  // hazard_pred (N,1)
    const float* dur   = (const float*)d_in[1];  // durations (N,)
    const float* ev    = (const float*)d_in[2];  // events (N,)
    float* out = (float*)d_out;

    static int configured = 0;
    if (!configured) {
        cudaFuncSetAttribute(cox_cluster_kernel,
                             cudaFuncAttributeMaxDynamicSharedMemorySize,
                             SMEM_BYTES);
        configured = 1;
    }
    cox_cluster_kernel<<<NB, TPB, SMEM_BYTES>>>(theta, dur, ev, out);
}

// round 11
// speedup vs baseline: 1.4076x; 1.4076x over previous
#include <cuda_runtime.h>
#include <cstdint>
#include <math.h>

#define N     16384
#define BKT   8192          // buckets (lambda = 2)
#define NB    16            // CTAs in ONE cluster (non-portable size)
#define TPB   1024          // 16384 threads total -> 1 item per thread
#define HPC   (BKT / NB)    // 512 histogram entries re-zeroed per CTA
#define EPT   (BKT / TPB)   // 8 histogram entries scanned per thread

#define SCALE     16777216.0f            // 2^24 fixed-point for e
#define INV_SCALE 5.9604644775390625e-8f // 2^-24

// ---- global scratch (L2; zero-init at load; re-zeroed each run) ----
__device__ unsigned long long g_H[BKT];  // (fixed_sum << 20) | count
__device__ float2 g_sorted[N];           // {duration, exp(theta)}; overwritten

// dynamic smem: Wp float[BKT] @0 (32KB), S ushort[BKT+2] @32768 (16KB)
#define SMEM_BYTES (32768 + 16384 + 64)
extern __shared__ char smem_raw[];

__device__ __forceinline__ void cluster_sync() {
    // arrive = release, wait = acquire at cluster scope: no explicit fences
    asm volatile("barrier.cluster.arrive.aligned;" ::: "memory");
    asm volatile("barrier.cluster.wait.aligned;" ::: "memory");
}

__device__ __forceinline__ int bucket_of(float d) {
    int b = (int)(d * (float)BKT);
    if (b >= BKT) b = BKT - 1;
    if (b < 0) b = 0;
    return b;
}

__global__ void __launch_bounds__(TPB, 1) __cluster_dims__(NB, 1, 1)
cox_cluster_kernel(const float* __restrict__ theta,
                   const float* __restrict__ dur,
                   const float* __restrict__ ev,
                   float* __restrict__ out) {
    float*          Wp = (float*)(smem_raw);                   // excl. prefix
    unsigned short* S  = (unsigned short*)(smem_raw + 32768);  // bucket starts

    __shared__ float warpTotF[32];
    __shared__ float warpPreF[32];
    __shared__ int   warpTotI[32];
    __shared__ int   warpPreI[32];
    __shared__ float s_total;

    const int t    = threadIdx.x;
    const int k    = blockIdx.x;
    const int g    = k * TPB + t;          // my single item
    const int lane = t & 31;
    const int wid  = t >> 5;

    // ---- Pass A: one packed 64-bit atomic; rank from return ----
    float th = theta[g];
    float d  = dur[g];
    float e_ = ev[g];
    float e  = __expf(th);
    int   b  = bucket_of(d);
    unsigned long long pk =
        ((unsigned long long)__float2ull_rn(e * SCALE) << 20) | 1ull;
    unsigned long long old = atomicAdd(&g_H[b], pk);
    int rank = (int)(old & 0xFFFFFull);
    float acc = e_ * th;
    if (g == 0) out[0] = 0.0f;             // ordered before final adds by B1/B2
    cluster_sync();                                            // B1

    // ---- Scan: every CTA redundantly scans all 8192 packed entries ----
    // thread t owns contiguous entries [8t, 8t+8)
    float wv[EPT]; int cv[EPT];
    const int e8 = t * EPT;
    {
        const ulonglong2* H2 = (const ulonglong2*)&g_H[e8];
        #pragma unroll
        for (int j = 0; j < EPT / 2; ++j) {
            ulonglong2 h = __ldcg(&H2[j]);
            wv[2*j]   = (float)(h.x >> 20) * INV_SCALE;
            cv[2*j]   = (int)(h.x & 0xFFFFFull);
            wv[2*j+1] = (float)(h.y >> 20) * INV_SCALE;
            cv[2*j+1] = (int)(h.y & 0xFFFFFull);
        }
    }
    float runW = 0.0f; int runC = 0;
    #pragma unroll
    for (int j = 0; j < EPT; ++j) { runW += wv[j]; runC += cv[j]; }
    float iW = runW; int iC = runC;
    #pragma unroll
    for (int off = 1; off < 32; off <<= 1) {
        float uW = __shfl_up_sync(0xFFFFFFFFu, iW, off);
        int   uC = __shfl_up_sync(0xFFFFFFFFu, iC, off);
        if (lane >= off) { iW += uW; iC += uC; }
    }
    if (lane == 31) { warpTotF[wid] = iW; warpTotI[wid] = iC; }
    __syncthreads();
    if (wid == 0) {
        float vF = warpTotF[lane]; int vI = warpTotI[lane];
        float wF = vF; int wI = vI;
        #pragma unroll
        for (int off = 1; off < 32; off <<= 1) {
            float uF = __shfl_up_sync(0xFFFFFFFFu, wF, off);
            int   uI = __shfl_up_sync(0xFFFFFFFFu, wI, off);
            if (lane >= off) { wF += uF; wI += uI; }
        }
        warpPreF[lane] = wF - vF;
        warpPreI[lane] = wI - vI;
        if (lane == 31) s_total = wF;
    }
    __syncthreads();
    float eW = warpPreF[wid] + (iW - runW);   // exclusive prefix at e8
    int   eC = warpPreI[wid] + (iC - runC);
    #pragma unroll
    for (int j = 0; j < EPT; ++j) {
        Wp[e8 + j] = eW;
        S[e8 + j]  = (unsigned short)eC;
        eW += wv[j];
        eC += cv[j];
    }
    if (t == TPB - 1) S[BKT] = (unsigned short)N;  // sentinel: start of bkt BKT
    const float total = s_total;
    __syncthreads();

    // ---- Pass B: scatter via precomputed rank (NO atomics) ----
    g_sorted[(int)S[b] + rank] = make_float2(d, e);
    cluster_sync();                                            // B2

    // ---- re-zero owned histogram segment (all reads done before B2) ----
    if (t < HPC) g_H[k * HPC + t] = 0ull;

    // ---- Phase 4: per-item risk (starts/prefix from smem, items from L2) ----
    {
        int s0 = (int)S[b];
        int s1 = (int)S[b + 1];
        float Sa = Wp[b];
        for (int s = s0; s < s1; ++s) {
            float2 v = __ldcg(&g_sorted[s]);
            if (v.x < d) Sa += v.y;           // strict <: self & ties excluded
        }
        float risk = total - Sa;              // sum over d_j >= d_i
        acc -= e_ * __logf(risk);
    }
    #pragma unroll
    for (int off = 16; off > 0; off >>= 1)
        acc += __shfl_down_sync(0xFFFFFFFFu, acc, off);
    if (lane == 0) atomicAdd(out, -acc / (float)N);
    // kernel exit flushes atomics; g_H left zeroed for next replay
}

extern "C" void kernel_launch(void* const* d_in, const int* in_sizes, int n_in,
                              void* d_out, int out_size) {
    const float* theta = (const float*)d_in[0];  // hazard_pred (N,1)
    const float* dur   = (const float*)d_in[1];  // durations (N,)
    const float* ev    = (const float*)d_in[2];  // events (N,)
    float* out = (float*)d_out;

    static int configured = 0;
    if (!configured) {
        cudaFuncSetAttribute(cox_cluster_kernel,
                             cudaFuncAttributeMaxDynamicSharedMemorySize,
                             SMEM_BYTES);
        cudaFuncSetAttribute(cox_cluster_kernel,
                             cudaFuncAttributeNonPortableClusterSizeAllowed, 1);
        configured = 1;
    }
    cox_cluster_kernel<<<NB, TPB, SMEM_BYTES>>>(theta, dur, ev, out);
}

// round 12
// speedup vs baseline: 1.6250x; 1.1544x over previous
#include <cuda_runtime.h>
#include <cstdint>
#include <math.h>

#define N     16384
#define BKT   4096          // buckets (lambda = 4)
#define NB    16            // CTAs in ONE cluster (non-portable size)
#define TPB   1024          // 16384 threads total -> 1 item per thread
#define HPC   (BKT / NB)    // 256 histogram entries re-zeroed per CTA
#define EPT   (BKT / TPB)   // 4 histogram entries scanned per thread

#define SCALE     16777216.0f            // 2^24 fixed-point for e
#define INV_SCALE 5.9604644775390625e-8f // 2^-24

// ---- global scratch (L2; zero-init at load; re-zeroed each run) ----
// packed entry: (fixed_sum << 20) | count.  Scan-safe: sum_total < 2^44,
// count_total = 16384 < 2^20 (no carry between fields).
__device__ unsigned long long g_H[BKT];
__device__ float2 g_sorted[N];           // {duration, exp(theta)}; overwritten

// dynamic smem: P ull[BKT+1] packed exclusive prefix (32KB + 8)
#define SMEM_BYTES (32768 + 16)
extern __shared__ char smem_raw[];

__device__ __forceinline__ void cluster_sync() {
    // arrive = release, wait = acquire at cluster scope: no explicit fences
    asm volatile("barrier.cluster.arrive.aligned;" ::: "memory");
    asm volatile("barrier.cluster.wait.aligned;" ::: "memory");
}

__device__ __forceinline__ int bucket_of(float d) {
    int b = (int)(d * (float)BKT);
    if (b >= BKT) b = BKT - 1;
    if (b < 0) b = 0;
    return b;
}

__global__ void __launch_bounds__(TPB, 1) __cluster_dims__(NB, 1, 1)
cox_cluster_kernel(const float* __restrict__ theta,
                   const float* __restrict__ dur,
                   const float* __restrict__ ev,
                   float* __restrict__ out) {
    unsigned long long* P = (unsigned long long*)(smem_raw); // excl. prefix

    __shared__ unsigned long long warpTot[32];
    __shared__ unsigned long long warpPre[32];
    __shared__ unsigned long long s_totalP;

    const int t    = threadIdx.x;
    const int k    = blockIdx.x;
    const int g    = k * TPB + t;          // my single item
    const int lane = t & 31;
    const int wid  = t >> 5;

    // ---- Pass A: one packed 64-bit atomic; within-bucket rank from return ----
    float th = theta[g];
    float d  = dur[g];
    float e_ = ev[g];
    float e  = __expf(th);
    int   b  = bucket_of(d);
    unsigned long long pk =
        ((unsigned long long)__float2ull_rn(e * SCALE) << 20) | 1ull;
    unsigned long long old = atomicAdd(&g_H[b], pk);
    int rank = (int)(old & 0xFFFFFull);
    float acc = e_ * th;
    if (g == 0) out[0] = 0.0f;             // ordered before final adds by B1/B2
    cluster_sync();                                            // B1

    // ---- Scan (packed domain): every CTA scans all 4096 entries ----
    // thread t owns contiguous entries [4t, 4t+4)
    unsigned long long h[EPT];
    const int e4 = t * EPT;
    {
        const ulonglong2* H2 = (const ulonglong2*)&g_H[e4];
        ulonglong2 a = __ldcg(&H2[0]);
        ulonglong2 c = __ldcg(&H2[1]);
        h[0] = a.x; h[1] = a.y; h[2] = c.x; h[3] = c.y;
    }
    unsigned long long run = h[0] + h[1] + h[2] + h[3];
    unsigned long long incl = run;
    #pragma unroll
    for (int off = 1; off < 32; off <<= 1) {
        unsigned long long u = __shfl_up_sync(0xFFFFFFFFu, incl, off);
        if (lane >= off) incl += u;
    }
    if (lane == 31) warpTot[wid] = incl;
    __syncthreads();
    if (wid == 0) {
        unsigned long long v = warpTot[lane];
        unsigned long long w = v;
        #pragma unroll
        for (int off = 1; off < 32; off <<= 1) {
            unsigned long long u = __shfl_up_sync(0xFFFFFFFFu, w, off);
            if (lane >= off) w += u;
        }
        warpPre[lane] = w - v;              // exclusive warp prefix
        if (lane == 31) s_totalP = w;       // packed grand total
    }
    __syncthreads();
    unsigned long long ex = warpPre[wid] + (incl - run);
    #pragma unroll
    for (int j = 0; j < EPT; ++j) {
        P[e4 + j] = ex;
        ex += h[j];
    }
    if (t == TPB - 1) P[BKT] = ex;          // sentinel: prefix past last bucket
    const float total = (float)(s_totalP >> 20) * INV_SCALE;
    __syncthreads();

    // ---- Pass B: scatter via prefix count + rank (NO atomics) ----
    const unsigned long long pb = P[b];
    const int s0 = (int)(pb & 0xFFFFFull);  // bucket start
    g_sorted[s0 + rank] = make_float2(d, e);
    cluster_sync();                                            // B2

    // ---- re-zero owned histogram segment (all reads done before B2) ----
    if (t < HPC) g_H[k * HPC + t] = 0ull;

    // ---- Phase 4: per-item risk (prefix from smem, items from L2) ----
    {
        const int s1 = (int)(P[b + 1] & 0xFFFFFull);   // bucket end
        float Sa = (float)(pb >> 20) * INV_SCALE;      // strictly-smaller mass
        #pragma unroll 2
        for (int s = s0; s < s1; ++s) {
            float2 v = __ldcg(&g_sorted[s]);
            if (v.x < d) Sa += v.y;          // strict <: self & ties excluded
        }
        float risk = total - Sa;             // sum over d_j >= d_i
        acc -= e_ * __logf(risk);
    }
    #pragma unroll
    for (int off = 16; off > 0; off >>= 1)
        acc += __shfl_down_sync(0xFFFFFFFFu, acc, off);
    if (lane == 0) atomicAdd(out, -acc / (float)N);
    // kernel exit flushes atomics; g_H left zeroed for next replay
}

extern "C" void kernel_launch(void* const* d_in, const int* in_sizes, int n_in,
                              void* d_out, int out_size) {
    const float* theta = (const float*)d_in[0];  // hazard_pred (N,1)
    const float* dur   = (const float*)d_in[1];  // durations (N,)
    const float* ev    = (const float*)d_in[2];  // events (N,)
    float* out = (float*)d_out;

    static int configured = 0;
    if (!configured) {
        cudaFuncSetAttribute(cox_cluster_kernel,
                             cudaFuncAttributeMaxDynamicSharedMemorySize,
                             SMEM_BYTES);
        cudaFuncSetAttribute(cox_cluster_kernel,
                             cudaFuncAttributeNonPortableClusterSizeAllowed, 1);
        configured = 1;
    }
    cox_cluster_kernel<<<NB, TPB, SMEM_BYTES>>>(theta, dur, ev, out);
}